// round 1
// baseline (speedup 1.0000x reference)
#include <cuda_runtime.h>
#include <stdint.h>

typedef unsigned long long u64;

#define DD 20
#define RPT 4            // rows per thread (2 packed f32x2 pairs)
#define TPB 128
#define MAXBLK 8192

// ---------------- device scratch (no allocs allowed) ----------------
__device__ float  g_M1[DD*DD];   // M1[k][m] = sum_j W[j,k]*Wi[j,m]
__device__ float  g_c1[DD];      // c1[m]    = sum_j b[j]*Wi[j,m] + 1
__device__ float  g_Wt[DD*DD];   // Wt[m][n] = W[n,m]  (for h3 = h2 @ W^T)
__device__ double g_psum[MAXBLK];
__device__ double g_pabs[MAXBLK];

// ---------------- packed f32x2 helpers ----------------
__device__ __forceinline__ u64 fma2(u64 a, u64 b, u64 c) {
    u64 d;
    asm("fma.rn.f32x2 %0, %1, %2, %3;" : "=l"(d) : "l"(a), "l"(b), "l"(c));
    return d;
}
__device__ __forceinline__ u64 add2(u64 a, u64 b) {
    u64 d;
    asm("add.rn.f32x2 %0, %1, %2;" : "=l"(d) : "l"(a), "l"(b));
    return d;
}
__device__ __forceinline__ u64 pack2(float lo, float hi) {
    u64 d;
    asm("mov.b64 %0, {%1, %2};" : "=l"(d) : "f"(lo), "f"(hi));
    return d;
}
__device__ __forceinline__ float lo2(u64 v) { return __uint_as_float((unsigned)v); }
__device__ __forceinline__ float hi2(u64 v) { return __uint_as_float((unsigned)(v >> 32)); }
__device__ __forceinline__ u64 relu2(u64 v) {
    return pack2(fmaxf(lo2(v), 0.0f), fmaxf(hi2(v), 0.0f));
}

// ---------------- setup: fold first two matmuls, transpose W ----------------
__global__ void setup_kernel(const float* __restrict__ W,
                             const float* __restrict__ b,
                             const float* __restrict__ Wi) {
    int t = threadIdx.x;
    if (t < DD * DD) {
        int k = t / DD, m = t % DD;
        double acc = 0.0;
        for (int j = 0; j < DD; j++)
            acc += (double)W[j * DD + k] * (double)Wi[j * DD + m];
        g_M1[t] = (float)acc;
        // Wt[m][n] = W[n][m]; here t = m*DD + n
        int mm = t / DD, n = t % DD;
        g_Wt[t] = W[n * DD + mm];
    }
    if (t < DD) {
        double acc = 0.0;
        for (int j = 0; j < DD; j++)
            acc += (double)b[j] * (double)Wi[j * DD + t];
        g_c1[t] = (float)(acc + 1.0);
    }
}

// ---------------- main: 4 rows/thread, f32x2 packed matvecs ----------------
__global__ void __launch_bounds__(TPB, 2)
main_kernel(const float* __restrict__ X, const float* __restrict__ b,
            long long nrows) {
    __shared__ u64 sM1[DD*DD];   // duplicated pairs (w,w)
    __shared__ u64 sWt[DD*DD];
    __shared__ u64 sc1[DD];
    __shared__ u64 sb[DD];

    int t = threadIdx.x;
    for (int i = t; i < DD * DD; i += TPB) {
        float v = g_M1[i]; sM1[i] = pack2(v, v);
        float w = g_Wt[i]; sWt[i] = pack2(w, w);
    }
    if (t < DD) {
        float v = g_c1[t]; sc1[t] = pack2(v, v);
        float w = b[t];    sb[t]  = pack2(w, w);
    }
    __syncthreads();

    long long base = ((long long)blockIdx.x * TPB + t) * RPT;
    u64 psum = 0ull, pabs = 0ull;   // packed (0.0f, 0.0f)

    if (base + RPT <= nrows) {
        // ---- load 4 contiguous rows (320B) as 20 float4 ----
        const float4* xr = (const float4*)(X + base * DD);
        float4 q[20];
        #pragma unroll
        for (int i = 0; i < 20; i++) q[i] = xr[i];
        const float* xf = (const float*)q;   // xf[r*20 + k]

        u64 x0[DD], x1[DD];
        #pragma unroll
        for (int k = 0; k < DD; k++) {
            x0[k] = pack2(xf[k],        xf[20 + k]);
            x1[k] = pack2(xf[40 + k],   xf[60 + k]);
        }

        // ---- h2 = relu(X @ M1 + c1) ----
        u64 h0[DD], h1v[DD];
        #pragma unroll
        for (int m = 0; m < DD; m++) { h0[m] = sc1[m]; h1v[m] = sc1[m]; }
        #pragma unroll
        for (int k = 0; k < DD; k++) {
            #pragma unroll
            for (int m = 0; m < DD; m++) {
                u64 w = sM1[k * DD + m];       // one LDS.64, feeds 2 FFMA2
                h0[m]  = fma2(x0[k], w, h0[m]);
                h1v[m] = fma2(x1[k], w, h1v[m]);
            }
        }
        #pragma unroll
        for (int m = 0; m < DD; m++) { h0[m] = relu2(h0[m]); h1v[m] = relu2(h1v[m]); }

        // ---- h3[n] = h2 @ W^T + b ; accumulate sum and |sum| ----
        #pragma unroll 4
        for (int n = 0; n < DD; n++) {
            u64 a0 = sb[n], a1 = sb[n];
            #pragma unroll
            for (int m = 0; m < DD; m++) {
                u64 w = sWt[m * DD + n];
                a0 = fma2(h0[m],  w, a0);
                a1 = fma2(h1v[m], w, a1);
            }
            psum = add2(psum, add2(a0, a1));
            u64 ab = add2(a0 & 0x7FFFFFFF7FFFFFFFull,
                          a1 & 0x7FFFFFFF7FFFFFFFull);
            pabs = add2(pabs, ab);
        }
    } else if (base < nrows) {
        // scalar tail (only if nrows % 4 != 0)
        for (long long r = base; r < nrows; r++) {
            float h2s[DD];
            for (int m = 0; m < DD; m++) {
                float acc = lo2(sc1[m]);
                for (int k = 0; k < DD; k++)
                    acc = fmaf(X[r * DD + k], lo2(sM1[k * DD + m]), acc);
                h2s[m] = fmaxf(acc, 0.0f);
            }
            for (int n = 0; n < DD; n++) {
                float acc = lo2(sb[n]);
                for (int m = 0; m < DD; m++)
                    acc = fmaf(h2s[m], lo2(sWt[m * DD + n]), acc);
                psum = add2(psum, pack2(acc, 0.0f));
                pabs = add2(pabs, pack2(fabsf(acc), 0.0f));
            }
        }
    }

    // ---- reduce: warp shuffle -> shared -> per-block partial ----
    float ts = lo2(psum) + hi2(psum);
    float ta = lo2(pabs) + hi2(pabs);
    #pragma unroll
    for (int o = 16; o > 0; o >>= 1) {
        ts += __shfl_down_sync(0xFFFFFFFFu, ts, o);
        ta += __shfl_down_sync(0xFFFFFFFFu, ta, o);
    }
    __shared__ double rs[TPB / 32], ra[TPB / 32];
    if ((t & 31) == 0) { rs[t >> 5] = (double)ts; ra[t >> 5] = (double)ta; }
    __syncthreads();
    if (t == 0) {
        double S = 0.0, A = 0.0;
        #pragma unroll
        for (int i = 0; i < TPB / 32; i++) { S += rs[i]; A += ra[i]; }
        g_psum[blockIdx.x] = S;
        g_pabs[blockIdx.x] = A;
    }
}

// ---------------- finalize: reduce partials, halving loop, write scalar ----
__global__ void final_kernel(float* __restrict__ out, int nb) {
    __shared__ double ss[1024], sa[1024];
    int t = threadIdx.x;
    double S = 0.0, A = 0.0;
    for (int i = t; i < nb; i += 1024) { S += g_psum[i]; A += g_pabs[i]; }
    ss[t] = S; sa[t] = A;
    __syncthreads();
    for (int o = 512; o > 0; o >>= 1) {
        if (t < o) { ss[t] += ss[t + o]; sa[t] += sa[t + o]; }
        __syncthreads();
    }
    if (t == 0) {
        float s = (float)sa[0];
        int k = 0;
        while (s > 1.0f && k < 300) { s *= 0.5f; k++; }
        out[0] = (float)ldexp(ss[0], -k);   // sum(h) * 2^-k, exact scale
    }
}

// ---------------- launch ----------------
extern "C" void kernel_launch(void* const* d_in, const int* in_sizes, int n_in,
                              void* d_out, int out_size) {
    const float* X  = (const float*)d_in[0];
    const float* W  = (const float*)d_in[1];
    const float* b  = (const float*)d_in[2];
    const float* Wi = (const float*)d_in[3];

    long long nrows = (long long)in_sizes[0] / DD;
    int nthreads = (int)((nrows + RPT - 1) / RPT);
    int nb = (nthreads + TPB - 1) / TPB;
    if (nb > MAXBLK) nb = MAXBLK;   // guard (not hit at B=1e6)

    setup_kernel<<<1, 512>>>(W, b, Wi);
    main_kernel<<<nb, TPB>>>(X, b, nrows);
    final_kernel<<<1, 1024>>>((float*)d_out, nb);
}